// round 1
// baseline (speedup 1.0000x reference)
#include <cuda_runtime.h>
#include <cstdint>

#define B_SZ 64
#define T_SZ 2048
#define I_SZ 256
#define H_SZ 256
#define O_SZ 128
#define M_SZ (B_SZ * T_SZ)   // 131072 rows

// Scratch (device globals: no allocations allowed)
__device__ float g_xp1[(size_t)M_SZ * H_SZ];   // 128 MB
__device__ float g_h1 [(size_t)M_SZ * H_SZ];   // 128 MB
__device__ float g_xp2[(size_t)M_SZ * O_SZ];   //  64 MB

// ---------------------------------------------------------------------------
// Packed fp32x2 FMA (Blackwell): 2 fp32 FMAs per issue -> 128 FMA/cyc/SM
// ---------------------------------------------------------------------------
__device__ __forceinline__ float2 ffma2(float2 a, float2 b, float2 c) {
    unsigned lo, hi;
    asm("{\n\t"
        ".reg .b64 ra, rb, rc;\n\t"
        "mov.b64 ra, {%2, %3};\n\t"
        "mov.b64 rb, {%4, %5};\n\t"
        "mov.b64 rc, {%6, %7};\n\t"
        "fma.rn.f32x2 rc, ra, rb, rc;\n\t"
        "mov.b64 {%0, %1}, rc;\n\t"
        "}"
        : "=r"(lo), "=r"(hi)
        : "r"(__float_as_uint(a.x)), "r"(__float_as_uint(a.y)),
          "r"(__float_as_uint(b.x)), "r"(__float_as_uint(b.y)),
          "r"(__float_as_uint(c.x)), "r"(__float_as_uint(c.y)));
    return make_float2(__uint_as_float(lo), __uint_as_float(hi));
}

// ---------------------------------------------------------------------------
// SGEMM with fused double-bias: C[M,N] = A[M,K] @ W[N,K]^T + bias_a + bias_b
// BM=128, BN=128, BK=16, 256 threads, 8x8 per thread (f32x2 packed).
// ---------------------------------------------------------------------------
__global__ __launch_bounds__(256, 2)
void sgemm_bias_kernel(const float* __restrict__ A,
                       const float* __restrict__ W,
                       const float* __restrict__ bias_a,
                       const float* __restrict__ bias_b,
                       float* __restrict__ C, int K, int N)
{
    constexpr int BM = 128, BN = 128, BK = 16;
    __shared__ float As[BK][BM];
    __shared__ float Bs[BK][BN];

    int tid = threadIdx.x;
    int bm = blockIdx.y * BM;
    int bn = blockIdx.x * BN;
    int tm = tid >> 4;        // 0..15
    int tn = tid & 15;        // 0..15

    float2 acc[8][4];
    #pragma unroll
    for (int i = 0; i < 8; i++)
        #pragma unroll
        for (int j = 0; j < 4; j++) acc[i][j] = make_float2(0.f, 0.f);

    const float* Ab = A + (size_t)bm * K;
    const float* Wb = W + (size_t)bn * K;

    for (int kt = 0; kt < K; kt += BK) {
        // Load A tile (128 x 16) transposed into As[k][m]
        #pragma unroll
        for (int it = 0; it < 2; it++) {
            int lid = tid * 2 + it;
            int row = lid >> 2, c4 = lid & 3;
            float4 v = *(const float4*)(Ab + (size_t)row * K + kt + c4 * 4);
            As[c4 * 4 + 0][row] = v.x;
            As[c4 * 4 + 1][row] = v.y;
            As[c4 * 4 + 2][row] = v.z;
            As[c4 * 4 + 3][row] = v.w;
        }
        // Load W tile (128 x 16) transposed into Bs[k][n]
        #pragma unroll
        for (int it = 0; it < 2; it++) {
            int lid = tid * 2 + it;
            int row = lid >> 2, c4 = lid & 3;
            float4 v = *(const float4*)(Wb + (size_t)row * K + kt + c4 * 4);
            Bs[c4 * 4 + 0][row] = v.x;
            Bs[c4 * 4 + 1][row] = v.y;
            Bs[c4 * 4 + 2][row] = v.z;
            Bs[c4 * 4 + 3][row] = v.w;
        }
        __syncthreads();

        #pragma unroll
        for (int kk = 0; kk < BK; kk++) {
            float4 a0 = *(const float4*)&As[kk][tm * 8];
            float4 a1 = *(const float4*)&As[kk][tm * 8 + 4];
            float4 b0 = *(const float4*)&Bs[kk][tn * 8];
            float4 b1 = *(const float4*)&Bs[kk][tn * 8 + 4];
            float av[8] = {a0.x, a0.y, a0.z, a0.w, a1.x, a1.y, a1.z, a1.w};
            float2 bv[4] = {make_float2(b0.x, b0.y), make_float2(b0.z, b0.w),
                            make_float2(b1.x, b1.y), make_float2(b1.z, b1.w)};
            #pragma unroll
            for (int i = 0; i < 8; i++) {
                float2 ai = make_float2(av[i], av[i]);
                #pragma unroll
                for (int j = 0; j < 4; j++)
                    acc[i][j] = ffma2(ai, bv[j], acc[i][j]);
            }
        }
        __syncthreads();
    }

    // Epilogue: add (bias_a + bias_b), store
    float2 bb[4];
    #pragma unroll
    for (int j = 0; j < 4; j++) {
        int n = bn + tn * 8 + j * 2;
        bb[j] = make_float2(bias_a[n] + bias_b[n], bias_a[n + 1] + bias_b[n + 1]);
    }
    #pragma unroll
    for (int i = 0; i < 8; i++) {
        int m = bm + tm * 8 + i;
        float* Crow = C + (size_t)m * N + bn + tn * 8;
        #pragma unroll
        for (int j = 0; j < 4; j++) {
            float2 v = make_float2(acc[i][j].x + bb[j].x, acc[i][j].y + bb[j].y);
            *(float2*)(Crow + j * 2) = v;
        }
    }
}

// ---------------------------------------------------------------------------
// Layer-1 scan: cluster of 2 CTAs per batch element. Each CTA owns 128 output
// rows of W_hh1 in registers (64 floats/thread, 512 threads). Full h (256)
// kept in SMEM in both CTAs; halves exchanged per step via st.shared::cluster.
// h layout: 4 chunks of 64 floats, chunk stride 68 (pad) for bank-conflict-free
// rotated LDS.128 reads.
// ---------------------------------------------------------------------------
__global__ void __cluster_dims__(2, 1, 1) __launch_bounds__(512, 1)
rnn_scan1_kernel(const float* __restrict__ W_hh,
                 const float* __restrict__ xp,
                 float* __restrict__ h1out)
{
    __shared__ float hbuf[2][4 * 68];

    int tid = threadIdx.x;
    int o_local = tid >> 2;     // 0..127
    int c = tid & 3;            // input chunk 0..3 (64 inputs each)
    unsigned r;
    asm("mov.u32 %0, %%cluster_ctarank;" : "=r"(r));
    int b = blockIdx.x >> 1;
    int o_global = (int)r * 128 + o_local;

    // Register-resident weights, stored in ROTATED order so the inner-loop
    // register index is compile-time (rotation lives in the SMEM address).
    float2 w2[32];
    {
        const float4* wp = (const float4*)(W_hh + (size_t)o_global * H_SZ + c * 64);
        #pragma unroll
        for (int j = 0; j < 16; j++) {
            int jj = (j + c * 4) & 15;
            float4 v = wp[jj];
            w2[2 * j]     = make_float2(v.x, v.y);
            w2[2 * j + 1] = make_float2(v.z, v.w);
        }
    }

    // h0 = 0 (full 256 in local copy)
    if (tid < 256) hbuf[0][(tid >> 6) * 68 + (tid & 63)] = 0.f;

    int wpos = (o_global >> 6) * 68 + (o_global & 63);
    uint32_t l0 = (uint32_t)__cvta_generic_to_shared(&hbuf[0][wpos]);
    uint32_t l1 = (uint32_t)__cvta_generic_to_shared(&hbuf[1][wpos]);
    uint32_t rem0, rem1;
    unsigned peer = r ^ 1u;
    asm("mapa.shared::cluster.u32 %0, %1, %2;" : "=r"(rem0) : "r"(l0), "r"(peer));
    asm("mapa.shared::cluster.u32 %0, %1, %2;" : "=r"(rem1) : "r"(l1), "r"(peer));

    const float* xpb = xp + (size_t)b * T_SZ * H_SZ + o_global;
    float* hob = h1out + (size_t)b * T_SZ * H_SZ + o_global;

    // all cluster CTAs initialized before first step
    asm volatile("barrier.cluster.arrive.aligned;\n\tbarrier.cluster.wait.aligned;" ::: "memory");

    int p = 0;
    for (int t = 0; t < T_SZ; t++) {
        float xv = 0.f;
        if (c == 0) xv = __ldg(xpb + (size_t)t * H_SZ);   // prefetch early

        const float* hb = &hbuf[p][c * 68];
        float2 a0 = make_float2(0.f, 0.f), a1 = a0, a2 = a0, a3 = a0;
        #pragma unroll
        for (int j = 0; j < 16; j++) {
            int jj = (j + c * 4) & 15;                     // bank-decorrelating rotation
            float4 hv = *(const float4*)(hb + jj * 4);
            float2 h01 = make_float2(hv.x, hv.y);
            float2 h23 = make_float2(hv.z, hv.w);
            if (j & 1) { a2 = ffma2(h01, w2[2 * j], a2); a3 = ffma2(h23, w2[2 * j + 1], a3); }
            else       { a0 = ffma2(h01, w2[2 * j], a0); a1 = ffma2(h23, w2[2 * j + 1], a1); }
        }
        float2 s2 = make_float2(a0.x + a1.x + a2.x + a3.x, a0.y + a1.y + a2.y + a3.y);
        float s = s2.x + s2.y;
        s += __shfl_xor_sync(0xffffffffu, s, 1);
        s += __shfl_xor_sync(0xffffffffu, s, 2);

        if (c == 0) {
            float v = tanhf(s + xv);
            hbuf[p ^ 1][wpos] = v;                         // local copy
            uint32_t ra = p ? rem0 : rem1;                 // peer copy (buffer p^1)
            asm volatile("st.shared::cluster.f32 [%0], %1;" :: "r"(ra), "f"(v) : "memory");
            hob[(size_t)t * H_SZ] = v;                     // h1 for layer-2 GEMM
        }
        // release/acquire cluster barrier: orders DSMEM stores, swaps buffers
        asm volatile("barrier.cluster.arrive.aligned;\n\tbarrier.cluster.wait.aligned;" ::: "memory");
        p ^= 1;
    }
}

// ---------------------------------------------------------------------------
// Layer-2 scan: one CTA per batch element (W_hh2 = 16K floats -> 32/thread).
// ---------------------------------------------------------------------------
__global__ __launch_bounds__(512, 1)
void rnn_scan2_kernel(const float* __restrict__ W_hh,
                      const float* __restrict__ xp,
                      float* __restrict__ out)
{
    __shared__ float obuf[2][4 * 36];

    int tid = threadIdx.x;
    int o = tid >> 2;           // 0..127
    int c = tid & 3;            // 32 inputs each
    int b = blockIdx.x;

    float2 w2[16];
    {
        const float4* wp = (const float4*)(W_hh + (size_t)o * O_SZ + c * 32);
        #pragma unroll
        for (int j = 0; j < 8; j++) {
            int jj = (j + c * 2) & 7;
            float4 v = wp[jj];
            w2[2 * j]     = make_float2(v.x, v.y);
            w2[2 * j + 1] = make_float2(v.z, v.w);
        }
    }

    if (tid < 128) obuf[0][(tid >> 5) * 36 + (tid & 31)] = 0.f;
    int wpos = (o >> 5) * 36 + (o & 31);

    const float* xpb = xp + (size_t)b * T_SZ * O_SZ + o;
    float* ob = out + (size_t)b * T_SZ * O_SZ + o;
    __syncthreads();

    int p = 0;
    for (int t = 0; t < T_SZ; t++) {
        float xv = 0.f;
        if (c == 0) xv = __ldg(xpb + (size_t)t * O_SZ);

        const float* hb = &obuf[p][c * 36];
        float2 a0 = make_float2(0.f, 0.f), a1 = a0;
        #pragma unroll
        for (int j = 0; j < 8; j++) {
            int jj = (j + c * 2) & 7;
            float4 hv = *(const float4*)(hb + jj * 4);
            a0 = ffma2(make_float2(hv.x, hv.y), w2[2 * j], a0);
            a1 = ffma2(make_float2(hv.z, hv.w), w2[2 * j + 1], a1);
        }
        float s = a0.x + a0.y + a1.x + a1.y;
        s += __shfl_xor_sync(0xffffffffu, s, 1);
        s += __shfl_xor_sync(0xffffffffu, s, 2);

        if (c == 0) {
            float v = tanhf(s + xv);
            obuf[p ^ 1][wpos] = v;
            ob[(size_t)t * O_SZ] = v;       // final output [B,T,O] flattened
        }
        __syncthreads();
        p ^= 1;
    }
}

// ---------------------------------------------------------------------------
extern "C" void kernel_launch(void* const* d_in, const int* in_sizes, int n_in,
                              void* d_out, int out_size)
{
    const float* x     = (const float*)d_in[0];
    const float* W_ih1 = (const float*)d_in[1];
    const float* W_hh1 = (const float*)d_in[2];
    const float* b_ih1 = (const float*)d_in[3];
    const float* b_hh1 = (const float*)d_in[4];
    const float* W_ih2 = (const float*)d_in[5];
    const float* W_hh2 = (const float*)d_in[6];
    const float* b_ih2 = (const float*)d_in[7];
    const float* b_hh2 = (const float*)d_in[8];
    float* out = (float*)d_out;

    float *xp1, *h1, *xp2;
    cudaGetSymbolAddress((void**)&xp1, g_xp1);
    cudaGetSymbolAddress((void**)&h1,  g_h1);
    cudaGetSymbolAddress((void**)&xp2, g_xp2);

    // Phase 1: xp1 = x @ W_ih1^T + (b_ih1 + b_hh1)   [131072 x 256]
    dim3 g1(H_SZ / 128, M_SZ / 128);
    sgemm_bias_kernel<<<g1, 256>>>(x, W_ih1, b_ih1, b_hh1, xp1, I_SZ, H_SZ);

    // Phase 2: layer-1 recurrent scan (cluster-2 per batch), emits h1
    rnn_scan1_kernel<<<B_SZ * 2, 512>>>(W_hh1, xp1, h1);

    // Phase 3: xp2 = h1 @ W_ih2^T + (b_ih2 + b_hh2)  [131072 x 128]
    dim3 g2(O_SZ / 128, M_SZ / 128);
    sgemm_bias_kernel<<<g2, 256>>>(h1, W_ih2, b_ih2, b_hh2, xp2, H_SZ, O_SZ);

    // Phase 4: layer-2 recurrent scan, writes final output
    rnn_scan2_kernel<<<B_SZ, 512>>>(W_hh2, xp2, out);
}

// round 2
// speedup vs baseline: 1.0165x; 1.0165x over previous
#include <cuda_runtime.h>
#include <cstdint>

#define B_SZ 64
#define T_SZ 2048
#define I_SZ 256
#define H_SZ 256
#define O_SZ 128
#define M_SZ (B_SZ * T_SZ)   // 131072 rows

// Scratch (device globals: no allocations allowed)
__device__ float g_xp1[(size_t)M_SZ * H_SZ];   // 128 MB
__device__ float g_h1 [(size_t)M_SZ * H_SZ];   // 128 MB
__device__ float g_xp2[(size_t)M_SZ * O_SZ];   //  64 MB

// ---------------------------------------------------------------------------
// Packed fp32x2 FMA (Blackwell): 2 fp32 FMAs per issue -> 128 FMA/cyc/SM.
// Clean "l" constraints: operands live in aligned register pairs, single
// FFMA2 in SASS, no surrounding MOVs.
// ---------------------------------------------------------------------------
union f2u { float2 f; unsigned long long u; };

__device__ __forceinline__ float2 ffma2(float2 a, float2 b, float2 c) {
    f2u A, Bv, C;
    A.f = a; Bv.f = b; C.f = c;
    asm("fma.rn.f32x2 %0, %1, %2, %3;"
        : "=l"(C.u) : "l"(A.u), "l"(Bv.u), "l"(C.u));
    return C.f;
}

// ---------------------------------------------------------------------------
// SGEMM with fused double-bias: C[M,N] = A[M,K] @ W[N,K]^T + bias_a + bias_b
// BM=128, BN=128, BK=16, 256 threads, 8x8 per thread (f32x2 packed).
// ---------------------------------------------------------------------------
__global__ __launch_bounds__(256, 2)
void sgemm_bias_kernel(const float* __restrict__ A,
                       const float* __restrict__ W,
                       const float* __restrict__ bias_a,
                       const float* __restrict__ bias_b,
                       float* __restrict__ C, int K, int N)
{
    constexpr int BM = 128, BN = 128, BK = 16;
    __shared__ float As[BK][BM];
    __shared__ float Bs[BK][BN];

    int tid = threadIdx.x;
    int bm = blockIdx.y * BM;
    int bn = blockIdx.x * BN;
    int tm = tid >> 4;        // 0..15
    int tn = tid & 15;        // 0..15

    float2 acc[8][4];
    #pragma unroll
    for (int i = 0; i < 8; i++)
        #pragma unroll
        for (int j = 0; j < 4; j++) acc[i][j] = make_float2(0.f, 0.f);

    const float* Ab = A + (size_t)bm * K;
    const float* Wb = W + (size_t)bn * K;

    for (int kt = 0; kt < K; kt += BK) {
        // Load A tile (128 x 16) transposed into As[k][m]
        #pragma unroll
        for (int it = 0; it < 2; it++) {
            int lid = tid * 2 + it;
            int row = lid >> 2, c4 = lid & 3;
            float4 v = *(const float4*)(Ab + (size_t)row * K + kt + c4 * 4);
            As[c4 * 4 + 0][row] = v.x;
            As[c4 * 4 + 1][row] = v.y;
            As[c4 * 4 + 2][row] = v.z;
            As[c4 * 4 + 3][row] = v.w;
        }
        // Load W tile (128 x 16) transposed into Bs[k][n]
        #pragma unroll
        for (int it = 0; it < 2; it++) {
            int lid = tid * 2 + it;
            int row = lid >> 2, c4 = lid & 3;
            float4 v = *(const float4*)(Wb + (size_t)row * K + kt + c4 * 4);
            Bs[c4 * 4 + 0][row] = v.x;
            Bs[c4 * 4 + 1][row] = v.y;
            Bs[c4 * 4 + 2][row] = v.z;
            Bs[c4 * 4 + 3][row] = v.w;
        }
        __syncthreads();

        #pragma unroll
        for (int kk = 0; kk < BK; kk++) {
            float4 a0 = *(const float4*)&As[kk][tm * 8];
            float4 a1 = *(const float4*)&As[kk][tm * 8 + 4];
            float4 b0 = *(const float4*)&Bs[kk][tn * 8];
            float4 b1 = *(const float4*)&Bs[kk][tn * 8 + 4];
            float av[8] = {a0.x, a0.y, a0.z, a0.w, a1.x, a1.y, a1.z, a1.w};
            float2 bv[4] = {make_float2(b0.x, b0.y), make_float2(b0.z, b0.w),
                            make_float2(b1.x, b1.y), make_float2(b1.z, b1.w)};
            #pragma unroll
            for (int i = 0; i < 8; i++) {
                float2 ai = make_float2(av[i], av[i]);
                #pragma unroll
                for (int j = 0; j < 4; j++)
                    acc[i][j] = ffma2(ai, bv[j], acc[i][j]);
            }
        }
        __syncthreads();
    }

    // Epilogue: add (bias_a + bias_b), store
    float2 bb[4];
    #pragma unroll
    for (int j = 0; j < 4; j++) {
        int n = bn + tn * 8 + j * 2;
        bb[j] = make_float2(bias_a[n] + bias_b[n], bias_a[n + 1] + bias_b[n + 1]);
    }
    #pragma unroll
    for (int i = 0; i < 8; i++) {
        int m = bm + tm * 8 + i;
        float* Crow = C + (size_t)m * N + bn + tn * 8;
        #pragma unroll
        for (int j = 0; j < 4; j++) {
            float2 v = make_float2(acc[i][j].x + bb[j].x, acc[i][j].y + bb[j].y);
            *(float2*)(Crow + j * 2) = v;
        }
    }
}

// ---------------------------------------------------------------------------
// Layer-1 scan: cluster of 2 CTAs per batch element. Each CTA owns 128 output
// rows of W_hh1 in registers (64 floats/thread, 512 threads). Full h (256)
// kept in SMEM in both CTAs; halves exchanged per step via st.shared::cluster.
// h layout: 4 chunks of 64 floats, chunk stride 68 (pad) for bank-conflict-free
// rotated LDS.128 reads.
// ---------------------------------------------------------------------------
__global__ void __cluster_dims__(2, 1, 1) __launch_bounds__(512, 1)
rnn_scan1_kernel(const float* __restrict__ W_hh,
                 const float* __restrict__ xp,
                 float* __restrict__ h1out)
{
    __shared__ float hbuf[2][4 * 68];

    int tid = threadIdx.x;
    int o_local = tid >> 2;     // 0..127
    int c = tid & 3;            // input chunk 0..3 (64 inputs each)
    unsigned r;
    asm("mov.u32 %0, %%cluster_ctarank;" : "=r"(r));
    int b = blockIdx.x >> 1;
    int o_global = (int)r * 128 + o_local;

    // Register-resident weights, stored in ROTATED order so the inner-loop
    // register index is compile-time (rotation lives in the SMEM address).
    float2 w2[32];
    {
        const float4* wp = (const float4*)(W_hh + (size_t)o_global * H_SZ + c * 64);
        #pragma unroll
        for (int j = 0; j < 16; j++) {
            int jj = (j + c * 4) & 15;
            float4 v = wp[jj];
            w2[2 * j]     = make_float2(v.x, v.y);
            w2[2 * j + 1] = make_float2(v.z, v.w);
        }
    }

    // h0 = 0 (full 256 in local copy)
    if (tid < 256) hbuf[0][(tid >> 6) * 68 + (tid & 63)] = 0.f;

    int wpos = (o_global >> 6) * 68 + (o_global & 63);
    uint32_t l0 = (uint32_t)__cvta_generic_to_shared(&hbuf[0][wpos]);
    uint32_t l1 = (uint32_t)__cvta_generic_to_shared(&hbuf[1][wpos]);
    uint32_t rem0, rem1;
    unsigned peer = r ^ 1u;
    asm("mapa.shared::cluster.u32 %0, %1, %2;" : "=r"(rem0) : "r"(l0), "r"(peer));
    asm("mapa.shared::cluster.u32 %0, %1, %2;" : "=r"(rem1) : "r"(l1), "r"(peer));

    const float* xpb = xp + (size_t)b * T_SZ * H_SZ + o_global;
    float* hob = h1out + (size_t)b * T_SZ * H_SZ + o_global;

    // all cluster CTAs initialized before first step
    asm volatile("barrier.cluster.arrive.aligned;\n\tbarrier.cluster.wait.aligned;" ::: "memory");

    int p = 0;
    for (int t = 0; t < T_SZ; t++) {
        float xv = 0.f;
        if (c == 0) xv = __ldg(xpb + (size_t)t * H_SZ);   // prefetch early

        const float* hb = &hbuf[p][c * 68];
        float2 a0 = make_float2(0.f, 0.f), a1 = a0, a2 = a0, a3 = a0;
        #pragma unroll
        for (int j = 0; j < 16; j++) {
            int jj = (j + c * 4) & 15;                     // bank-decorrelating rotation
            float4 hv = *(const float4*)(hb + jj * 4);
            float2 h01 = make_float2(hv.x, hv.y);
            float2 h23 = make_float2(hv.z, hv.w);
            if (j & 1) { a2 = ffma2(h01, w2[2 * j], a2); a3 = ffma2(h23, w2[2 * j + 1], a3); }
            else       { a0 = ffma2(h01, w2[2 * j], a0); a1 = ffma2(h23, w2[2 * j + 1], a1); }
        }
        float2 s2 = make_float2(a0.x + a1.x + a2.x + a3.x, a0.y + a1.y + a2.y + a3.y);
        float s = s2.x + s2.y;
        s += __shfl_xor_sync(0xffffffffu, s, 1);
        s += __shfl_xor_sync(0xffffffffu, s, 2);

        if (c == 0) {
            float v = tanhf(s + xv);
            hbuf[p ^ 1][wpos] = v;                         // local copy
            uint32_t ra = p ? rem0 : rem1;                 // peer copy (buffer p^1)
            asm volatile("st.shared::cluster.f32 [%0], %1;" :: "r"(ra), "f"(v) : "memory");
            hob[(size_t)t * H_SZ] = v;                     // h1 for layer-2 GEMM
        }
        // release/acquire cluster barrier: orders DSMEM stores, swaps buffers
        asm volatile("barrier.cluster.arrive.aligned;\n\tbarrier.cluster.wait.aligned;" ::: "memory");
        p ^= 1;
    }
}

// ---------------------------------------------------------------------------
// Layer-2 scan: one CTA per batch element (W_hh2 = 16K floats -> 32/thread).
// ---------------------------------------------------------------------------
__global__ __launch_bounds__(512, 1)
void rnn_scan2_kernel(const float* __restrict__ W_hh,
                      const float* __restrict__ xp,
                      float* __restrict__ out)
{
    __shared__ float obuf[2][4 * 36];

    int tid = threadIdx.x;
    int o = tid >> 2;           // 0..127
    int c = tid & 3;            // 32 inputs each
    int b = blockIdx.x;

    float2 w2[16];
    {
        const float4* wp = (const float4*)(W_hh + (size_t)o * O_SZ + c * 32);
        #pragma unroll
        for (int j = 0; j < 8; j++) {
            int jj = (j + c * 2) & 7;
            float4 v = wp[jj];
            w2[2 * j]     = make_float2(v.x, v.y);
            w2[2 * j + 1] = make_float2(v.z, v.w);
        }
    }

    if (tid < 128) obuf[0][(tid >> 5) * 36 + (tid & 31)] = 0.f;
    int wpos = (o >> 5) * 36 + (o & 31);

    const float* xpb = xp + (size_t)b * T_SZ * O_SZ + o;
    float* ob = out + (size_t)b * T_SZ * O_SZ + o;
    __syncthreads();

    int p = 0;
    for (int t = 0; t < T_SZ; t++) {
        float xv = 0.f;
        if (c == 0) xv = __ldg(xpb + (size_t)t * O_SZ);

        const float* hb = &obuf[p][c * 36];
        float2 a0 = make_float2(0.f, 0.f), a1 = a0;
        #pragma unroll
        for (int j = 0; j < 8; j++) {
            int jj = (j + c * 2) & 7;
            float4 hv = *(const float4*)(hb + jj * 4);
            a0 = ffma2(make_float2(hv.x, hv.y), w2[2 * j], a0);
            a1 = ffma2(make_float2(hv.z, hv.w), w2[2 * j + 1], a1);
        }
        float s = a0.x + a0.y + a1.x + a1.y;
        s += __shfl_xor_sync(0xffffffffu, s, 1);
        s += __shfl_xor_sync(0xffffffffu, s, 2);

        if (c == 0) {
            float v = tanhf(s + xv);
            obuf[p ^ 1][wpos] = v;
            ob[(size_t)t * O_SZ] = v;       // final output [B,T,O] flattened
        }
        __syncthreads();
        p ^= 1;
    }
}

// ---------------------------------------------------------------------------
extern "C" void kernel_launch(void* const* d_in, const int* in_sizes, int n_in,
                              void* d_out, int out_size)
{
    const float* x     = (const float*)d_in[0];
    const float* W_ih1 = (const float*)d_in[1];
    const float* W_hh1 = (const float*)d_in[2];
    const float* b_ih1 = (const float*)d_in[3];
    const float* b_hh1 = (const float*)d_in[4];
    const float* W_ih2 = (const float*)d_in[5];
    const float* W_hh2 = (const float*)d_in[6];
    const float* b_ih2 = (const float*)d_in[7];
    const float* b_hh2 = (const float*)d_in[8];
    float* out = (float*)d_out;

    float *xp1, *h1, *xp2;
    cudaGetSymbolAddress((void**)&xp1, g_xp1);
    cudaGetSymbolAddress((void**)&h1,  g_h1);
    cudaGetSymbolAddress((void**)&xp2, g_xp2);

    // Phase 1: xp1 = x @ W_ih1^T + (b_ih1 + b_hh1)   [131072 x 256]
    dim3 g1(H_SZ / 128, M_SZ / 128);
    sgemm_bias_kernel<<<g1, 256>>>(x, W_ih1, b_ih1, b_hh1, xp1, I_SZ, H_SZ);

    // Phase 2: layer-1 recurrent scan (cluster-2 per batch), emits h1
    rnn_scan1_kernel<<<B_SZ * 2, 512>>>(W_hh1, xp1, h1);

    // Phase 3: xp2 = h1 @ W_ih2^T + (b_ih2 + b_hh2)  [131072 x 128]
    dim3 g2(O_SZ / 128, M_SZ / 128);
    sgemm_bias_kernel<<<g2, 256>>>(h1, W_ih2, b_ih2, b_hh2, xp2, H_SZ, O_SZ);

    // Phase 4: layer-2 recurrent scan, writes final output
    rnn_scan2_kernel<<<B_SZ, 512>>>(W_hh2, xp2, out);
}

// round 3
// speedup vs baseline: 1.2411x; 1.2210x over previous
#include <cuda_runtime.h>
#include <cstdint>

#define B_SZ 64
#define T_SZ 2048
#define I_SZ 256
#define H_SZ 256
#define O_SZ 128
#define M_SZ (B_SZ * T_SZ)   // 131072 rows

// Scratch (device globals: no allocations allowed)
__device__ float g_xp1[(size_t)M_SZ * H_SZ];   // 128 MB
__device__ float g_h1 [(size_t)M_SZ * H_SZ];   // 128 MB
__device__ float g_xp2[(size_t)M_SZ * O_SZ];   //  64 MB

// ---------------------------------------------------------------------------
// Packed fp32x2 FMA (Blackwell): 2 fp32 FMAs per issue -> 128 FMA/cyc/SM.
// ---------------------------------------------------------------------------
union f2u { float2 f; unsigned long long u; };

__device__ __forceinline__ float2 ffma2(float2 a, float2 b, float2 c) {
    f2u A, Bv, C;
    A.f = a; Bv.f = b; C.f = c;
    asm("fma.rn.f32x2 %0, %1, %2, %3;"
        : "=l"(C.u) : "l"(A.u), "l"(Bv.u), "l"(C.u));
    return C.f;
}

// ---------------------------------------------------------------------------
// SGEMM with fused double-bias: C[M,N] = A[M,K] @ W[N,K]^T + bias_a + bias_b
// BM=128, BN=128, BK=16, 256 threads, 8x8 per thread (f32x2 packed).
// ---------------------------------------------------------------------------
__global__ __launch_bounds__(256, 2)
void sgemm_bias_kernel(const float* __restrict__ A,
                       const float* __restrict__ W,
                       const float* __restrict__ bias_a,
                       const float* __restrict__ bias_b,
                       float* __restrict__ C, int K, int N)
{
    constexpr int BM = 128, BN = 128, BK = 16;
    __shared__ float As[BK][BM];
    __shared__ float Bs[BK][BN];

    int tid = threadIdx.x;
    int bm = blockIdx.y * BM;
    int bn = blockIdx.x * BN;
    int tm = tid >> 4;        // 0..15
    int tn = tid & 15;        // 0..15

    float2 acc[8][4];
    #pragma unroll
    for (int i = 0; i < 8; i++)
        #pragma unroll
        for (int j = 0; j < 4; j++) acc[i][j] = make_float2(0.f, 0.f);

    const float* Ab = A + (size_t)bm * K;
    const float* Wb = W + (size_t)bn * K;

    for (int kt = 0; kt < K; kt += BK) {
        #pragma unroll
        for (int it = 0; it < 2; it++) {
            int lid = tid * 2 + it;
            int row = lid >> 2, c4 = lid & 3;
            float4 v = *(const float4*)(Ab + (size_t)row * K + kt + c4 * 4);
            As[c4 * 4 + 0][row] = v.x;
            As[c4 * 4 + 1][row] = v.y;
            As[c4 * 4 + 2][row] = v.z;
            As[c4 * 4 + 3][row] = v.w;
        }
        #pragma unroll
        for (int it = 0; it < 2; it++) {
            int lid = tid * 2 + it;
            int row = lid >> 2, c4 = lid & 3;
            float4 v = *(const float4*)(Wb + (size_t)row * K + kt + c4 * 4);
            Bs[c4 * 4 + 0][row] = v.x;
            Bs[c4 * 4 + 1][row] = v.y;
            Bs[c4 * 4 + 2][row] = v.z;
            Bs[c4 * 4 + 3][row] = v.w;
        }
        __syncthreads();

        #pragma unroll
        for (int kk = 0; kk < BK; kk++) {
            float4 a0 = *(const float4*)&As[kk][tm * 8];
            float4 a1 = *(const float4*)&As[kk][tm * 8 + 4];
            float4 b0 = *(const float4*)&Bs[kk][tn * 8];
            float4 b1 = *(const float4*)&Bs[kk][tn * 8 + 4];
            float av[8] = {a0.x, a0.y, a0.z, a0.w, a1.x, a1.y, a1.z, a1.w};
            float2 bv[4] = {make_float2(b0.x, b0.y), make_float2(b0.z, b0.w),
                            make_float2(b1.x, b1.y), make_float2(b1.z, b1.w)};
            #pragma unroll
            for (int i = 0; i < 8; i++) {
                float2 ai = make_float2(av[i], av[i]);
                #pragma unroll
                for (int j = 0; j < 4; j++)
                    acc[i][j] = ffma2(ai, bv[j], acc[i][j]);
            }
        }
        __syncthreads();
    }

    float2 bb[4];
    #pragma unroll
    for (int j = 0; j < 4; j++) {
        int n = bn + tn * 8 + j * 2;
        bb[j] = make_float2(bias_a[n] + bias_b[n], bias_a[n + 1] + bias_b[n + 1]);
    }
    #pragma unroll
    for (int i = 0; i < 8; i++) {
        int m = bm + tm * 8 + i;
        float* Crow = C + (size_t)m * N + bn + tn * 8;
        #pragma unroll
        for (int j = 0; j < 4; j++) {
            float2 v = make_float2(acc[i][j].x + bb[j].x, acc[i][j].y + bb[j].y);
            *(float2*)(Crow + j * 2) = v;
        }
    }
}

// ---------------------------------------------------------------------------
// Layer-1 scan: cluster of 2 CTAs per batch element. Register-resident W_hh
// halves; h exchanged per step via st.shared::cluster + cluster barrier.
// NEW: xp stream prefetched 4 steps ahead through a rotating register buffer
// so the per-step DRAM latency is off the recurrent critical path.
// ---------------------------------------------------------------------------
__global__ void __cluster_dims__(2, 1, 1) __launch_bounds__(512, 1)
rnn_scan1_kernel(const float* __restrict__ W_hh,
                 const float* __restrict__ xp,
                 float* __restrict__ h1out)
{
    __shared__ float hbuf[2][4 * 68];

    int tid = threadIdx.x;
    int o_local = tid >> 2;     // 0..127
    int c = tid & 3;            // input chunk 0..3 (64 inputs each)
    unsigned r;
    asm("mov.u32 %0, %%cluster_ctarank;" : "=r"(r));
    int b = blockIdx.x >> 1;
    int o_global = (int)r * 128 + o_local;

    float2 w2[32];
    {
        const float4* wp = (const float4*)(W_hh + (size_t)o_global * H_SZ + c * 64);
        #pragma unroll
        for (int j = 0; j < 16; j++) {
            int jj = (j + c * 4) & 15;
            float4 v = wp[jj];
            w2[2 * j]     = make_float2(v.x, v.y);
            w2[2 * j + 1] = make_float2(v.z, v.w);
        }
    }

    if (tid < 256) hbuf[0][(tid >> 6) * 68 + (tid & 63)] = 0.f;

    int wpos = (o_global >> 6) * 68 + (o_global & 63);
    uint32_t l0 = (uint32_t)__cvta_generic_to_shared(&hbuf[0][wpos]);
    uint32_t l1 = (uint32_t)__cvta_generic_to_shared(&hbuf[1][wpos]);
    uint32_t rem0, rem1;
    unsigned peer = r ^ 1u;
    asm("mapa.shared::cluster.u32 %0, %1, %2;" : "=r"(rem0) : "r"(l0), "r"(peer));
    asm("mapa.shared::cluster.u32 %0, %1, %2;" : "=r"(rem1) : "r"(l1), "r"(peer));

    const float* xpb = xp + (size_t)b * T_SZ * H_SZ + o_global;
    float* hob = h1out + (size_t)b * T_SZ * H_SZ + o_global;

    // Prefetch pipeline: xp values for steps t..t+3 live in pf[0..3].
    float pf[4];
    #pragma unroll
    for (int i = 0; i < 4; i++)
        pf[i] = (c == 0) ? __ldg(xpb + (size_t)i * H_SZ) : 0.f;

    asm volatile("barrier.cluster.arrive.aligned;\n\tbarrier.cluster.wait.aligned;" ::: "memory");

    int p = 0;
    #pragma unroll 4
    for (int t = 0; t < T_SZ; t++) {
        float xv = pf[t & 3];
        // Issue prefetch for t+4 immediately: ~4 step-times to complete.
        if (c == 0 && t + 4 < T_SZ)
            pf[t & 3] = __ldg(xpb + (size_t)(t + 4) * H_SZ);

        const float* hb = &hbuf[p][c * 68];
        float2 a0 = make_float2(0.f, 0.f), a1 = a0, a2 = a0, a3 = a0;
        #pragma unroll
        for (int j = 0; j < 16; j++) {
            int jj = (j + c * 4) & 15;                     // bank-decorrelating rotation
            float4 hv = *(const float4*)(hb + jj * 4);
            float2 h01 = make_float2(hv.x, hv.y);
            float2 h23 = make_float2(hv.z, hv.w);
            if (j & 1) { a2 = ffma2(h01, w2[2 * j], a2); a3 = ffma2(h23, w2[2 * j + 1], a3); }
            else       { a0 = ffma2(h01, w2[2 * j], a0); a1 = ffma2(h23, w2[2 * j + 1], a1); }
        }
        float2 s2 = make_float2(a0.x + a1.x + a2.x + a3.x, a0.y + a1.y + a2.y + a3.y);
        float s = s2.x + s2.y;
        s += __shfl_xor_sync(0xffffffffu, s, 1);
        s += __shfl_xor_sync(0xffffffffu, s, 2);

        if (c == 0) {
            float v = tanhf(s + xv);
            hbuf[p ^ 1][wpos] = v;                         // local copy
            uint32_t ra = p ? rem0 : rem1;                 // peer copy (buffer p^1)
            asm volatile("st.shared::cluster.f32 [%0], %1;" :: "r"(ra), "f"(v) : "memory");
            hob[(size_t)t * H_SZ] = v;                     // h1 for layer-2 GEMM
        }
        asm volatile("barrier.cluster.arrive.aligned;\n\tbarrier.cluster.wait.aligned;" ::: "memory");
        p ^= 1;
    }
}

// ---------------------------------------------------------------------------
// Layer-2 scan: one CTA per batch element, same 4-deep xp prefetch.
// ---------------------------------------------------------------------------
__global__ __launch_bounds__(512, 1)
void rnn_scan2_kernel(const float* __restrict__ W_hh,
                      const float* __restrict__ xp,
                      float* __restrict__ out)
{
    __shared__ float obuf[2][4 * 36];

    int tid = threadIdx.x;
    int o = tid >> 2;           // 0..127
    int c = tid & 3;            // 32 inputs each
    int b = blockIdx.x;

    float2 w2[16];
    {
        const float4* wp = (const float4*)(W_hh + (size_t)o * O_SZ + c * 32);
        #pragma unroll
        for (int j = 0; j < 8; j++) {
            int jj = (j + c * 2) & 7;
            float4 v = wp[jj];
            w2[2 * j]     = make_float2(v.x, v.y);
            w2[2 * j + 1] = make_float2(v.z, v.w);
        }
    }

    if (tid < 128) obuf[0][(tid >> 5) * 36 + (tid & 31)] = 0.f;
    int wpos = (o >> 5) * 36 + (o & 31);

    const float* xpb = xp + (size_t)b * T_SZ * O_SZ + o;
    float* ob = out + (size_t)b * T_SZ * O_SZ + o;

    float pf[4];
    #pragma unroll
    for (int i = 0; i < 4; i++)
        pf[i] = (c == 0) ? __ldg(xpb + (size_t)i * O_SZ) : 0.f;

    __syncthreads();

    int p = 0;
    #pragma unroll 4
    for (int t = 0; t < T_SZ; t++) {
        float xv = pf[t & 3];
        if (c == 0 && t + 4 < T_SZ)
            pf[t & 3] = __ldg(xpb + (size_t)(t + 4) * O_SZ);

        const float* hb = &obuf[p][c * 36];
        float2 a0 = make_float2(0.f, 0.f), a1 = a0;
        #pragma unroll
        for (int j = 0; j < 8; j++) {
            int jj = (j + c * 2) & 7;
            float4 hv = *(const float4*)(hb + jj * 4);
            a0 = ffma2(make_float2(hv.x, hv.y), w2[2 * j], a0);
            a1 = ffma2(make_float2(hv.z, hv.w), w2[2 * j + 1], a1);
        }
        float s = a0.x + a0.y + a1.x + a1.y;
        s += __shfl_xor_sync(0xffffffffu, s, 1);
        s += __shfl_xor_sync(0xffffffffu, s, 2);

        if (c == 0) {
            float v = tanhf(s + xv);
            obuf[p ^ 1][wpos] = v;
            ob[(size_t)t * O_SZ] = v;       // final output [B,T,O] flattened
        }
        __syncthreads();
        p ^= 1;
    }
}

// ---------------------------------------------------------------------------
extern "C" void kernel_launch(void* const* d_in, const int* in_sizes, int n_in,
                              void* d_out, int out_size)
{
    const float* x     = (const float*)d_in[0];
    const float* W_ih1 = (const float*)d_in[1];
    const float* W_hh1 = (const float*)d_in[2];
    const float* b_ih1 = (const float*)d_in[3];
    const float* b_hh1 = (const float*)d_in[4];
    const float* W_ih2 = (const float*)d_in[5];
    const float* W_hh2 = (const float*)d_in[6];
    const float* b_ih2 = (const float*)d_in[7];
    const float* b_hh2 = (const float*)d_in[8];
    float* out = (float*)d_out;

    float *xp1, *h1, *xp2;
    cudaGetSymbolAddress((void**)&xp1, g_xp1);
    cudaGetSymbolAddress((void**)&h1,  g_h1);
    cudaGetSymbolAddress((void**)&xp2, g_xp2);

    // Phase 1: xp1 = x @ W_ih1^T + (b_ih1 + b_hh1)   [131072 x 256]
    dim3 g1(H_SZ / 128, M_SZ / 128);
    sgemm_bias_kernel<<<g1, 256>>>(x, W_ih1, b_ih1, b_hh1, xp1, I_SZ, H_SZ);

    // Phase 2: layer-1 recurrent scan (cluster-2 per batch), emits h1
    rnn_scan1_kernel<<<B_SZ * 2, 512>>>(W_hh1, xp1, h1);

    // Phase 3: xp2 = h1 @ W_ih2^T + (b_ih2 + b_hh2)  [131072 x 128]
    dim3 g2(O_SZ / 128, M_SZ / 128);
    sgemm_bias_kernel<<<g2, 256>>>(h1, W_ih2, b_ih2, b_hh2, xp2, H_SZ, O_SZ);

    // Phase 4: layer-2 recurrent scan, writes final output
    rnn_scan2_kernel<<<B_SZ, 512>>>(W_hh2, xp2, out);
}